// round 8
// baseline (speedup 1.0000x reference)
#include <cuda_runtime.h>
#include <cuda_bf16.h>
#include <stdint.h>

#define NN 20000
#define EE 320000
#define DD 512
#define BN_EPS 1e-5f

__device__ float4 g_X4[NN * 128];        // x          [N, 512]
__device__ float4 g_XC4[NN * 256];       // [agg|x_bn] [N, 1024]
__device__ float  g_invdeg[NN];
__device__ __nv_bfloat16 g_Wh[4 * 512 * 1024];   // W hi bf16 [l][n][k]
__device__ __nv_bfloat16 g_Wl[4 * 512 * 1024];   // W lo bf16

__device__ __forceinline__ float4 f4add(float4 a, float4 b) {
    return make_float4(a.x + b.x, a.y + b.y, a.z + b.z, a.w + b.w);
}

// ---------------------------------------------------------------------------
__global__ void k_zero_deg() {
    int i = blockIdx.x * blockDim.x + threadIdx.x;
    if (i < NN) g_invdeg[i] = 0.f;
}
__global__ void k_count(const int* __restrict__ dst) {
    int e = blockIdx.x * blockDim.x + threadIdx.x;
    if (e < EE) atomicAdd(&g_invdeg[dst[e]], 1.f);
}
__global__ void k_invdeg() {
    int i = blockIdx.x * blockDim.x + threadIdx.x;
    if (i < NN) g_invdeg[i] = 1.f / fmaxf(g_invdeg[i], 1.f);
}

__global__ void k_embed(const int* __restrict__ tok, const int* __restrict__ pos,
                        const float4* __restrict__ ve, const float4* __restrict__ pe) {
    unsigned t = blockIdx.x * blockDim.x + threadIdx.x;
    unsigned i = t >> 7, c = t & 127u;
    if (i < NN) {
        g_X4[i * 128 + c] = f4add(ve[(unsigned)tok[i] * 128 + c],
                                  pe[(unsigned)pos[i] * 128 + c]);
    }
}

__global__ void k_bn(const float4* __restrict__ ga, const float4* __restrict__ be,
                     const float4* __restrict__ me, const float4* __restrict__ va) {
    unsigned t = blockIdx.x * blockDim.x + threadIdx.x;
    unsigned i = t >> 7, c = t & 127u;
    if (i >= NN) return;
    float4 x = g_X4[i * 128 + c];
    float4 g = ga[c], b = be[c], m = me[c], v = va[c];
    float4 y;
    y.x = (x.x - m.x) * (g.x * rsqrtf(v.x + BN_EPS)) + b.x;
    y.y = (x.y - m.y) * (g.y * rsqrtf(v.y + BN_EPS)) + b.y;
    y.z = (x.z - m.z) * (g.z * rsqrtf(v.z + BN_EPS)) + b.z;
    y.w = (x.w - m.w) * (g.w * rsqrtf(v.w + BN_EPS)) + b.w;
    g_XC4[i * 256 + 128 + c] = y;
    g_XC4[i * 256 + c] = make_float4(0.f, 0.f, 0.f, 0.f);
}

__global__ void k_scatter(const int* __restrict__ src, const int* __restrict__ dst) {
    unsigned t = blockIdx.x * blockDim.x + threadIdx.x;
    unsigned e = t >> 7, c = t & 127u;
    if (e < EE) {
        unsigned s = (unsigned)__ldg(src + e);
        unsigned d = (unsigned)__ldg(dst + e);
        float4 v = g_XC4[s * 256 + 128 + c];
        float* p = (float*)&g_XC4[d * 256 + c];
        asm volatile("red.global.add.v4.f32 [%0], {%1,%2,%3,%4};"
                     :: "l"(p), "f"(v.x), "f"(v.y), "f"(v.z), "f"(v.w)
                     : "memory");
    }
}

// ---------------------------------------------------------------------------
// One-time per launch: split W = [Wrel | Wroot] into bf16 hi/lo planes.
// g_Wh/g_Wl layout [l][n][k], k in [0,1024): 0-511 -> Wrel, 512-1023 -> Wroot
// ---------------------------------------------------------------------------
__global__ void k_wconv(const float* __restrict__ Wrel, const float* __restrict__ Wroot) {
    unsigned t = blockIdx.x * blockDim.x + threadIdx.x;   // one per 4 elems
    if (t >= 4u * 512u * 1024u / 4u) return;
    unsigned base = t * 4u;
    unsigned l = base >> 19;                  // /(512*1024)
    unsigned rem = base & 0x7FFFFu;
    unsigned n = rem >> 10;
    unsigned k = rem & 1023u;
    const float* srcp = (k < 512u)
        ? (Wrel + ((size_t)l * 512 + n) * 512 + k)
        : (Wroot + ((size_t)l * 512 + n) * 512 + (k - 512u));
    float4 v = *(const float4*)srcp;
    __nv_bfloat162 h01 = __floats2bfloat162_rn(v.x, v.y);
    __nv_bfloat162 h23 = __floats2bfloat162_rn(v.z, v.w);
    float2 f01 = __bfloat1622float2(h01);
    float2 f23 = __bfloat1622float2(h23);
    __nv_bfloat162 l01 = __floats2bfloat162_rn(v.x - f01.x, v.y - f01.y);
    __nv_bfloat162 l23 = __floats2bfloat162_rn(v.z - f23.x, v.w - f23.y);
    *(uint2*)&g_Wh[base] = make_uint2(*(unsigned*)&h01, *(unsigned*)&h23);
    *(uint2*)&g_Wl[base] = make_uint2(*(unsigned*)&l01, *(unsigned*)&l23);
}

// ===========================================================================
// mma.sync bf16 GEMM, 3-term split, CTA 128x128, Kc=32, double-buffered.
// 8 warps (2m x 4n), warp tile 64x32. B preconverted bf16 (no in-loop cvt).
// smem rows padded to 80 B -> conflict-free ldmatrix.
// ===========================================================================
#define ROWB 80
#define S_AH 0
#define S_AL 10240
#define S_BH 20480
#define S_BL 30720
#define STAGE 40960
#define SMEM_DYN 81920

__device__ __forceinline__ uint32_t smem_u32(const void* p) {
    uint32_t a;
    asm("{ .reg .u64 t; cvta.to.shared.u64 t, %1; cvt.u32.u64 %0, t; }"
        : "=r"(a) : "l"(p));
    return a;
}
__device__ __forceinline__ void ldm_x4(uint32_t* r, uint32_t addr) {
    asm volatile("ldmatrix.sync.aligned.m8n8.x4.shared.b16 {%0,%1,%2,%3}, [%4];"
                 : "=r"(r[0]), "=r"(r[1]), "=r"(r[2]), "=r"(r[3]) : "r"(addr));
}
__device__ __forceinline__ void mma16816(float* c, const uint32_t* a,
                                         uint32_t b0, uint32_t b1) {
    asm volatile(
        "mma.sync.aligned.m16n8k16.row.col.f32.bf16.bf16.f32 "
        "{%0,%1,%2,%3}, {%4,%5,%6,%7}, {%8,%9}, {%0,%1,%2,%3};"
        : "+f"(c[0]), "+f"(c[1]), "+f"(c[2]), "+f"(c[3])
        : "r"(a[0]), "r"(a[1]), "r"(a[2]), "r"(a[3]), "r"(b0), "r"(b1));
}
__device__ __forceinline__ unsigned pack_hl(float a, float b, unsigned& lo) {
    __nv_bfloat162 h = __floats2bfloat162_rn(a, b);
    float2 hf = __bfloat1622float2(h);
    __nv_bfloat162 l = __floats2bfloat162_rn(a - hf.x, b - hf.y);
    lo = *reinterpret_cast<unsigned*>(&l);
    return *reinterpret_cast<unsigned*>(&h);
}

__global__ __launch_bounds__(256, 1) void k_gemm_mma(
    int lidx, const float* __restrict__ bias, float* __restrict__ outp, int writeX) {
    extern __shared__ char sm[];
    const uint32_t smb = smem_u32(sm);

    const int tid = threadIdx.x;
    const int w = tid >> 5, lane = tid & 31;
    const int row0 = blockIdx.y * 128;
    const int nb0 = blockIdx.x * 128;

    // ---- loader mapping: row = tid>>1 (0..127), hf = 16-float/32-byte half ----
    const int arow = tid >> 1;
    const int hf = tid & 1;
    const int agr = row0 + arow;
    const bool aval = agr < NN;
    const float ascale = aval ? g_invdeg[agr] : 0.f;
    const char* Wh = (const char*)(g_Wh + ((size_t)lidx * 512 + nb0) * 1024);
    const char* Wl = (const char*)(g_Wl + ((size_t)lidx * 512 + nb0) * 1024);

    // ---- compute mapping: warp grid 2m x 4n, warp tile 64x32 ----
    const int wm0 = (w >> 2) * 64;
    const int wn0 = (w & 3) * 32;
    const int l8 = lane & 7, lq = lane >> 3;

    float acc[4][4][4];
#pragma unroll
    for (int i = 0; i < 4; i++)
#pragma unroll
        for (int j = 0; j < 4; j++)
#pragma unroll
            for (int k = 0; k < 4; k++) acc[i][j][k] = 0.f;

    float4 af[4];
    uint4 bhr[2], blr[2];

#define LOAD_CHUNK(C)                                                         \
    {                                                                         \
        const int c_ = (C);                                                   \
        if (aval) {                                                           \
            const float4* p = &g_XC4[(size_t)agr * 256 + c_ * 8 + hf * 4];    \
            af[0] = __ldg(p); af[1] = __ldg(p + 1);                           \
            af[2] = __ldg(p + 2); af[3] = __ldg(p + 3);                       \
            if (c_ < 16) {                                                    \
                af[0].x *= ascale; af[0].y *= ascale; af[0].z *= ascale; af[0].w *= ascale; \
                af[1].x *= ascale; af[1].y *= ascale; af[1].z *= ascale; af[1].w *= ascale; \
                af[2].x *= ascale; af[2].y *= ascale; af[2].z *= ascale; af[2].w *= ascale; \
                af[3].x *= ascale; af[3].y *= ascale; af[3].z *= ascale; af[3].w *= ascale; \
            }                                                                 \
        } else {                                                              \
            af[0] = af[1] = af[2] = af[3] = make_float4(0.f, 0.f, 0.f, 0.f);  \
        }                                                                     \
        const char* bh = Wh + arow * 2048 + c_ * 64 + hf * 32;                \
        const char* bl = Wl + arow * 2048 + c_ * 64 + hf * 32;                \
        bhr[0] = __ldg((const uint4*)bh); bhr[1] = __ldg((const uint4*)(bh + 16)); \
        blr[0] = __ldg((const uint4*)bl); blr[1] = __ldg((const uint4*)(bl + 16)); \
    }

#define STORE_STAGE(S)                                                        \
    {                                                                         \
        char* base = sm + (S) * STAGE + arow * ROWB + hf * 32;                \
        unsigned h[8], l[8];                                                  \
        h[0] = pack_hl(af[0].x, af[0].y, l[0]);                               \
        h[1] = pack_hl(af[0].z, af[0].w, l[1]);                               \
        h[2] = pack_hl(af[1].x, af[1].y, l[2]);                               \
        h[3] = pack_hl(af[1].z, af[1].w, l[3]);                               \
        h[4] = pack_hl(af[2].x, af[2].y, l[4]);                               \
        h[5] = pack_hl(af[2].z, af[2].w, l[5]);                               \
        h[6] = pack_hl(af[3].x, af[3].y, l[6]);                               \
        h[7] = pack_hl(af[3].z, af[3].w, l[7]);                               \
        *(uint4*)(base + S_AH) = make_uint4(h[0], h[1], h[2], h[3]);          \
        *(uint4*)(base + S_AH + 16) = make_uint4(h[4], h[5], h[6], h[7]);     \
        *(uint4*)(base + S_AL) = make_uint4(l[0], l[1], l[2], l[3]);          \
        *(uint4*)(base + S_AL + 16) = make_uint4(l[4], l[5], l[6], l[7]);     \
        *(uint4*)(base + S_BH) = bhr[0];                                      \
        *(uint4*)(base + S_BH + 16) = bhr[1];                                 \
        *(uint4*)(base + S_BL) = blr[0];                                      \
        *(uint4*)(base + S_BL + 16) = blr[1];                                 \
    }

    LOAD_CHUNK(0);
    STORE_STAGE(0);
    __syncthreads();

#pragma unroll 1
    for (int c = 0; c < 32; ++c) {
        const int s = c & 1;
        if (c < 31) LOAD_CHUNK(c + 1);

        const uint32_t sb = smb + s * STAGE;
#pragma unroll
        for (int ks = 0; ks < 2; ++ks) {
            const int kb = ks * 32;
            uint32_t ah[4][4], al[4][4], bh[2][4], bl[2][4];
            const int ar = wm0 + (lq & 1) * 8 + l8;
            const uint32_t akb = kb + (lq >> 1) * 16;
#pragma unroll
            for (int mi = 0; mi < 4; mi++) {
                uint32_t addr = sb + (ar + mi * 16) * ROWB + akb;
                ldm_x4(ah[mi], addr + S_AH);
                ldm_x4(al[mi], addr + S_AL);
            }
            const int br = wn0 + (lq >> 1) * 8 + l8;
            const uint32_t bkb = kb + (lq & 1) * 16;
#pragma unroll
            for (int ng = 0; ng < 2; ng++) {
                uint32_t addr = sb + (br + ng * 16) * ROWB + bkb;
                ldm_x4(bh[ng], addr + S_BH);
                ldm_x4(bl[ng], addr + S_BL);
            }
#pragma unroll
            for (int mi = 0; mi < 4; mi++)
#pragma unroll
                for (int ni = 0; ni < 4; ni++) {
                    const int g = ni >> 1, o = (ni & 1) * 2;
                    mma16816(acc[mi][ni], ah[mi], bh[g][o], bh[g][o + 1]);
                    mma16816(acc[mi][ni], ah[mi], bl[g][o], bl[g][o + 1]);
                    mma16816(acc[mi][ni], al[mi], bh[g][o], bh[g][o + 1]);
                }
        }

        if (c < 31) STORE_STAGE(s ^ 1);
        __syncthreads();
    }
#undef LOAD_CHUNK
#undef STORE_STAGE

    // ---- epilogue: bias + relu, direct float2 stores ----
    float* O = writeX ? (float*)g_X4 : outp;
    const int lg = lane >> 2, lt = lane & 3;
#pragma unroll
    for (int ni = 0; ni < 4; ni++) {
        const int col = nb0 + wn0 + ni * 8 + lt * 2;
        const float b0 = __ldg(&bias[col]);
        const float b1 = __ldg(&bias[col + 1]);
#pragma unroll
        for (int mi = 0; mi < 4; mi++) {
            const int r0 = row0 + wm0 + mi * 16 + lg;
            if (r0 < NN) {
                float2 v;
                v.x = fmaxf(acc[mi][ni][0] + b0, 0.f);
                v.y = fmaxf(acc[mi][ni][1] + b1, 0.f);
                *(float2*)&O[(size_t)r0 * 512 + col] = v;
            }
            const int r1 = r0 + 8;
            if (r1 < NN) {
                float2 v;
                v.x = fmaxf(acc[mi][ni][2] + b0, 0.f);
                v.y = fmaxf(acc[mi][ni][3] + b1, 0.f);
                *(float2*)&O[(size_t)r1 * 512 + col] = v;
            }
        }
    }
}

// ---------------------------------------------------------------------------
extern "C" void kernel_launch(void* const* d_in, const int* in_sizes, int n_in,
                              void* d_out, int out_size) {
    (void)in_sizes; (void)n_in; (void)out_size;
    const int*   tokens = (const int*)d_in[0];
    const int*   pos    = (const int*)d_in[1];
    const int*   ei     = (const int*)d_in[2];
    const int*   src    = ei;
    const int*   dst    = ei + EE;
    const float* ve     = (const float*)d_in[3];
    const float* pe     = (const float*)d_in[4];
    const float* gamma  = (const float*)d_in[5];
    const float* beta   = (const float*)d_in[6];
    const float* mean   = (const float*)d_in[7];
    const float* var    = (const float*)d_in[8];
    const float* Wrel   = (const float*)d_in[9];
    const float* brel   = (const float*)d_in[10];
    const float* Wroot  = (const float*)d_in[11];
    float*       out    = (float*)d_out;

    cudaFuncSetAttribute(k_gemm_mma, cudaFuncAttributeMaxDynamicSharedMemorySize,
                         SMEM_DYN);

    k_zero_deg<<<(NN + 255) / 256, 256>>>();
    k_count<<<(EE + 255) / 256, 256>>>(dst);
    k_invdeg<<<(NN + 255) / 256, 256>>>();
    k_embed<<<(NN * 128) / 256, 256>>>(tokens, pos, (const float4*)ve, (const float4*)pe);
    k_wconv<<<(4 * 512 * 1024 / 4 + 255) / 256, 256>>>(Wrel, Wroot);

    for (int l = 0; l < 4; l++) {
        k_bn<<<(NN * 128) / 256, 256>>>(
            (const float4*)(gamma + l * DD), (const float4*)(beta + l * DD),
            (const float4*)(mean + l * DD), (const float4*)(var + l * DD));
        k_scatter<<<(EE * 128) / 256, 256>>>(src, dst);
        k_gemm_mma<<<dim3(4, 157), 256, SMEM_DYN>>>(
            l, brel + l * DD, out, (l == 3) ? 0 : 1);
    }
}

// round 9
// speedup vs baseline: 1.1762x; 1.1762x over previous
#include <cuda_runtime.h>
#include <cuda_bf16.h>
#include <stdint.h>

#define NN 20000
#define EE 320000
#define DD 512
#define BN_EPS 1e-5f

__device__ float4 g_X4[NN * 128];        // x          [N, 512]
__device__ float4 g_XC4[NN * 256];       // [agg|x_bn] [N, 1024] fp32
__device__ float  g_invdeg[NN];
__device__ __nv_bfloat16 g_Ah[(size_t)NN * 1024];   // A hi bf16 [N][1024]
__device__ __nv_bfloat16 g_Al[(size_t)NN * 1024];   // A lo bf16
__device__ __nv_bfloat16 g_Wh[4 * 512 * 1024];      // W hi bf16 [l][n][k]
__device__ __nv_bfloat16 g_Wl[4 * 512 * 1024];      // W lo bf16

__device__ __forceinline__ float4 f4add(float4 a, float4 b) {
    return make_float4(a.x + b.x, a.y + b.y, a.z + b.z, a.w + b.w);
}

// ---------------------------------------------------------------------------
__global__ void k_zero_deg() {
    int i = blockIdx.x * blockDim.x + threadIdx.x;
    if (i < NN) g_invdeg[i] = 0.f;
}
__global__ void k_count(const int* __restrict__ dst) {
    int e = blockIdx.x * blockDim.x + threadIdx.x;
    if (e < EE) atomicAdd(&g_invdeg[dst[e]], 1.f);
}
__global__ void k_invdeg() {
    int i = blockIdx.x * blockDim.x + threadIdx.x;
    if (i < NN) g_invdeg[i] = 1.f / fmaxf(g_invdeg[i], 1.f);
}

__global__ void k_embed(const int* __restrict__ tok, const int* __restrict__ pos,
                        const float4* __restrict__ ve, const float4* __restrict__ pe) {
    unsigned t = blockIdx.x * blockDim.x + threadIdx.x;
    unsigned i = t >> 7, c = t & 127u;
    if (i < NN) {
        g_X4[i * 128 + c] = f4add(ve[(unsigned)tok[i] * 128 + c],
                                  pe[(unsigned)pos[i] * 128 + c]);
    }
}

__device__ __forceinline__ unsigned pack_hl(float a, float b, unsigned& lo) {
    __nv_bfloat162 h = __floats2bfloat162_rn(a, b);
    float2 hf = __bfloat1622float2(h);
    __nv_bfloat162 l = __floats2bfloat162_rn(a - hf.x, b - hf.y);
    lo = *reinterpret_cast<unsigned*>(&l);
    return *reinterpret_cast<unsigned*>(&h);
}

// BN (eval) -> XC fp32 second half (scatter source), bf16 hi/lo A cols 512-1023,
// zero agg accumulator.
__global__ void k_bn(const float4* __restrict__ ga, const float4* __restrict__ be,
                     const float4* __restrict__ me, const float4* __restrict__ va) {
    unsigned t = blockIdx.x * blockDim.x + threadIdx.x;
    unsigned i = t >> 7, c = t & 127u;
    if (i >= NN) return;
    float4 x = g_X4[i * 128 + c];
    float4 g = ga[c], b = be[c], m = me[c], v = va[c];
    float4 y;
    y.x = (x.x - m.x) * (g.x * rsqrtf(v.x + BN_EPS)) + b.x;
    y.y = (x.y - m.y) * (g.y * rsqrtf(v.y + BN_EPS)) + b.y;
    y.z = (x.z - m.z) * (g.z * rsqrtf(v.z + BN_EPS)) + b.z;
    y.w = (x.w - m.w) * (g.w * rsqrtf(v.w + BN_EPS)) + b.w;
    g_XC4[i * 256 + 128 + c] = y;
    g_XC4[i * 256 + c] = make_float4(0.f, 0.f, 0.f, 0.f);
    unsigned l0, l1;
    unsigned h0 = pack_hl(y.x, y.y, l0);
    unsigned h1 = pack_hl(y.z, y.w, l1);
    size_t o = (size_t)i * 1024 + 512 + c * 4;
    *(uint2*)&g_Ah[o] = make_uint2(h0, h1);
    *(uint2*)&g_Al[o] = make_uint2(l0, l1);
}

__global__ void k_scatter(const int* __restrict__ src, const int* __restrict__ dst) {
    unsigned t = blockIdx.x * blockDim.x + threadIdx.x;
    unsigned e = t >> 7, c = t & 127u;
    if (e < EE) {
        unsigned s = (unsigned)__ldg(src + e);
        unsigned d = (unsigned)__ldg(dst + e);
        float4 v = g_XC4[s * 256 + 128 + c];
        float* p = (float*)&g_XC4[d * 256 + c];
        asm volatile("red.global.add.v4.f32 [%0], {%1,%2,%3,%4};"
                     :: "l"(p), "f"(v.x), "f"(v.y), "f"(v.z), "f"(v.w)
                     : "memory");
    }
}

// agg * invdeg -> bf16 hi/lo A cols 0-511
__global__ void k_aggconv() {
    unsigned t = blockIdx.x * blockDim.x + threadIdx.x;
    unsigned i = t >> 7, c = t & 127u;
    if (i >= NN) return;
    float s = g_invdeg[i];
    float4 v = g_XC4[i * 256 + c];
    v.x *= s; v.y *= s; v.z *= s; v.w *= s;
    unsigned l0, l1;
    unsigned h0 = pack_hl(v.x, v.y, l0);
    unsigned h1 = pack_hl(v.z, v.w, l1);
    size_t o = (size_t)i * 1024 + c * 4;
    *(uint2*)&g_Ah[o] = make_uint2(h0, h1);
    *(uint2*)&g_Al[o] = make_uint2(l0, l1);
}

// One-time: split W = [Wrel | Wroot] into bf16 hi/lo planes [l][n][1024].
__global__ void k_wconv(const float* __restrict__ Wrel, const float* __restrict__ Wroot) {
    unsigned t = blockIdx.x * blockDim.x + threadIdx.x;
    if (t >= 4u * 512u * 1024u / 4u) return;
    unsigned base = t * 4u;
    unsigned l = base >> 19;
    unsigned rem = base & 0x7FFFFu;
    unsigned n = rem >> 10;
    unsigned k = rem & 1023u;
    const float* srcp = (k < 512u)
        ? (Wrel + ((size_t)l * 512 + n) * 512 + k)
        : (Wroot + ((size_t)l * 512 + n) * 512 + (k - 512u));
    float4 v = *(const float4*)srcp;
    unsigned l0, l1;
    unsigned h0 = pack_hl(v.x, v.y, l0);
    unsigned h1 = pack_hl(v.z, v.w, l1);
    *(uint2*)&g_Wh[base] = make_uint2(h0, h1);
    *(uint2*)&g_Wl[base] = make_uint2(l0, l1);
}

// ===========================================================================
// mma.sync bf16 GEMM, 3-term split, CTA 128x128, Kc=32.
// cp.async 3-stage pipeline, ONE __syncthreads per chunk, zero in-loop cvt.
// 8 warps (2m x 4n), warp tile 64x32. ROWB=80 -> conflict-free ldmatrix.
// ===========================================================================
#define ROWB 80
#define S_AH 0
#define S_AL 10240
#define S_BH 20480
#define S_BL 30720
#define STAGE 40960
#define SMEM_DYN 122880

__device__ __forceinline__ uint32_t smem_u32(const void* p) {
    uint32_t a;
    asm("{ .reg .u64 t; cvta.to.shared.u64 t, %1; cvt.u32.u64 %0, t; }"
        : "=r"(a) : "l"(p));
    return a;
}
__device__ __forceinline__ void cpa16(uint32_t dst, const void* src, int sbytes) {
    asm volatile("cp.async.ca.shared.global [%0], [%1], 16, %2;"
                 :: "r"(dst), "l"(src), "r"(sbytes) : "memory");
}
__device__ __forceinline__ void ldm_x4(uint32_t* r, uint32_t addr) {
    asm volatile("ldmatrix.sync.aligned.m8n8.x4.shared.b16 {%0,%1,%2,%3}, [%4];"
                 : "=r"(r[0]), "=r"(r[1]), "=r"(r[2]), "=r"(r[3]) : "r"(addr));
}
__device__ __forceinline__ void mma16816(float* c, const uint32_t* a,
                                         uint32_t b0, uint32_t b1) {
    asm volatile(
        "mma.sync.aligned.m16n8k16.row.col.f32.bf16.bf16.f32 "
        "{%0,%1,%2,%3}, {%4,%5,%6,%7}, {%8,%9}, {%0,%1,%2,%3};"
        : "+f"(c[0]), "+f"(c[1]), "+f"(c[2]), "+f"(c[3])
        : "r"(a[0]), "r"(a[1]), "r"(a[2]), "r"(a[3]), "r"(b0), "r"(b1));
}

__global__ __launch_bounds__(256, 1) void k_gemm_mma(
    int lidx, const float* __restrict__ bias, float* __restrict__ outp, int writeX) {
    extern __shared__ char sm[];
    const uint32_t smb = smem_u32(sm);

    const int tid = threadIdx.x;
    const int w = tid >> 5, lane = tid & 31;
    const int row0 = blockIdx.y * 128;
    const int nb0 = blockIdx.x * 128;

    // ---- async-copy mapping: row = tid>>1, 32B half = (tid&1)*32 ----
    const int crow = tid >> 1;
    const int csp = (tid & 1) * 32;
    const int agr = row0 + crow;
    const int abytes = (agr < NN) ? 16 : 0;
    const char* pAh = (const char*)g_Ah + ((size_t)agr * 2048) + csp;
    const char* pAl = (const char*)g_Al + ((size_t)agr * 2048) + csp;
    const char* pWh = (const char*)(g_Wh + ((size_t)lidx * 512 + nb0 + crow) * 1024) + csp;
    const char* pWl = (const char*)(g_Wl + ((size_t)lidx * 512 + nb0 + crow) * 1024) + csp;
    const uint32_t sdst = smb + crow * ROWB + csp;

#define ISSUE(C)                                                              \
    {                                                                         \
        const int c_ = (C);                                                   \
        const uint32_t sb_ = ((c_) % 3) * STAGE;                              \
        const int go_ = c_ * 64;                                              \
        cpa16(sdst + sb_ + S_AH,      pAh + go_,      abytes);                \
        cpa16(sdst + sb_ + S_AH + 16, pAh + go_ + 16, abytes);                \
        cpa16(sdst + sb_ + S_AL,      pAl + go_,      abytes);                \
        cpa16(sdst + sb_ + S_AL + 16, pAl + go_ + 16, abytes);                \
        cpa16(sdst + sb_ + S_BH,      pWh + go_,      16);                    \
        cpa16(sdst + sb_ + S_BH + 16, pWh + go_ + 16, 16);                    \
        cpa16(sdst + sb_ + S_BL,      pWl + go_,      16);                    \
        cpa16(sdst + sb_ + S_BL + 16, pWl + go_ + 16, 16);                    \
        asm volatile("cp.async.commit_group;" ::: "memory");                  \
    }

    // ---- compute mapping: warp grid 2m x 4n, warp tile 64x32 ----
    const int wm0 = (w >> 2) * 64;
    const int wn0 = (w & 3) * 32;
    const int l8 = lane & 7, lq = lane >> 3;

    float acc[4][4][4];
#pragma unroll
    for (int i = 0; i < 4; i++)
#pragma unroll
        for (int j = 0; j < 4; j++)
#pragma unroll
            for (int k = 0; k < 4; k++) acc[i][j][k] = 0.f;

    ISSUE(0);
    ISSUE(1);

#pragma unroll 1
    for (int c = 0; c < 32; ++c) {
        if (c < 30) {
            asm volatile("cp.async.wait_group 1;" ::: "memory");
        } else {
            asm volatile("cp.async.wait_group 0;" ::: "memory");
        }
        __syncthreads();
        if (c < 30) ISSUE(c + 2);

        const uint32_t sb = smb + (c % 3) * STAGE;
#pragma unroll
        for (int ks = 0; ks < 2; ++ks) {
            const int kb = ks * 32;
            uint32_t ah[4][4], al[4][4], bh[2][4], bl[2][4];
            const int ar = wm0 + (lq & 1) * 8 + l8;
            const uint32_t akb = kb + (lq >> 1) * 16;
#pragma unroll
            for (int mi = 0; mi < 4; mi++) {
                uint32_t addr = sb + (ar + mi * 16) * ROWB + akb;
                ldm_x4(ah[mi], addr + S_AH);
                ldm_x4(al[mi], addr + S_AL);
            }
            const int br = wn0 + (lq >> 1) * 8 + l8;
            const uint32_t bkb = kb + (lq & 1) * 16;
#pragma unroll
            for (int ng = 0; ng < 2; ng++) {
                uint32_t addr = sb + (br + ng * 16) * ROWB + bkb;
                ldm_x4(bh[ng], addr + S_BH);
                ldm_x4(bl[ng], addr + S_BL);
            }
#pragma unroll
            for (int mi = 0; mi < 4; mi++)
#pragma unroll
                for (int ni = 0; ni < 4; ni++) {
                    const int g = ni >> 1, o = (ni & 1) * 2;
                    mma16816(acc[mi][ni], ah[mi], bh[g][o], bh[g][o + 1]);
                    mma16816(acc[mi][ni], ah[mi], bl[g][o], bl[g][o + 1]);
                    mma16816(acc[mi][ni], al[mi], bh[g][o], bh[g][o + 1]);
                }
        }
    }
#undef ISSUE

    // ---- epilogue: bias + relu, direct float2 stores ----
    float* O = writeX ? (float*)g_X4 : outp;
    const int lg = lane >> 2, lt = lane & 3;
#pragma unroll
    for (int ni = 0; ni < 4; ni++) {
        const int col = nb0 + wn0 + ni * 8 + lt * 2;
        const float b0 = __ldg(&bias[col]);
        const float b1 = __ldg(&bias[col + 1]);
#pragma unroll
        for (int mi = 0; mi < 4; mi++) {
            const int r0 = row0 + wm0 + mi * 16 + lg;
            if (r0 < NN) {
                float2 v;
                v.x = fmaxf(acc[mi][ni][0] + b0, 0.f);
                v.y = fmaxf(acc[mi][ni][1] + b1, 0.f);
                *(float2*)&O[(size_t)r0 * 512 + col] = v;
            }
            const int r1 = r0 + 8;
            if (r1 < NN) {
                float2 v;
                v.x = fmaxf(acc[mi][ni][2] + b0, 0.f);
                v.y = fmaxf(acc[mi][ni][3] + b1, 0.f);
                *(float2*)&O[(size_t)r1 * 512 + col] = v;
            }
        }
    }
}

// ---------------------------------------------------------------------------
extern "C" void kernel_launch(void* const* d_in, const int* in_sizes, int n_in,
                              void* d_out, int out_size) {
    (void)in_sizes; (void)n_in; (void)out_size;
    const int*   tokens = (const int*)d_in[0];
    const int*   pos    = (const int*)d_in[1];
    const int*   ei     = (const int*)d_in[2];
    const int*   src    = ei;
    const int*   dst    = ei + EE;
    const float* ve     = (const float*)d_in[3];
    const float* pe     = (const float*)d_in[4];
    const float* gamma  = (const float*)d_in[5];
    const float* beta   = (const float*)d_in[6];
    const float* mean   = (const float*)d_in[7];
    const float* var    = (const float*)d_in[8];
    const float* Wrel   = (const float*)d_in[9];
    const float* brel   = (const float*)d_in[10];
    const float* Wroot  = (const float*)d_in[11];
    float*       out    = (float*)d_out;

    cudaFuncSetAttribute(k_gemm_mma, cudaFuncAttributeMaxDynamicSharedMemorySize,
                         SMEM_DYN);

    k_zero_deg<<<(NN + 255) / 256, 256>>>();
    k_count<<<(EE + 255) / 256, 256>>>(dst);
    k_invdeg<<<(NN + 255) / 256, 256>>>();
    k_embed<<<(NN * 128) / 256, 256>>>(tokens, pos, (const float4*)ve, (const float4*)pe);
    k_wconv<<<(4 * 512 * 1024 / 4 + 255) / 256, 256>>>(Wrel, Wroot);

    for (int l = 0; l < 4; l++) {
        k_bn<<<(NN * 128) / 256, 256>>>(
            (const float4*)(gamma + l * DD), (const float4*)(beta + l * DD),
            (const float4*)(mean + l * DD), (const float4*)(var + l * DD));
        k_scatter<<<(EE * 128) / 256, 256>>>(src, dst);
        k_aggconv<<<(NN * 128) / 256, 256>>>();
        k_gemm_mma<<<dim3(4, 157), 256, SMEM_DYN>>>(
            l, brel + l * DD, out, (l == 3) ? 0 : 1);
    }
}

// round 11
// speedup vs baseline: 1.6284x; 1.3846x over previous
#include <cuda_runtime.h>
#include <cuda_bf16.h>
#include <stdint.h>

#define NN 20000
#define EE 320000
#define DD 512
#define BN_EPS 1e-5f

__device__ float4 g_X4[NN * 128];        // x     [N, 512] fp32
__device__ float4 g_Xbn[NN * 128];       // x_bn  [N, 512] fp32 (gather source)
__device__ float  g_invdeg[NN];
__device__ int    g_degi[NN];
__device__ int    g_cursor[NN];
__device__ int    g_rowptr[NN + 1];
__device__ int    g_csrc[EE];
__device__ __nv_bfloat16 g_Ah[(size_t)NN * 1024];   // A hi bf16 [N][1024]
__device__ __nv_bfloat16 g_Al[(size_t)NN * 1024];   // A lo bf16
__device__ __nv_bfloat16 g_Wh[4 * 512 * 1024];      // W hi bf16 [l][n][k]
__device__ __nv_bfloat16 g_Wl[4 * 512 * 1024];      // W lo bf16

__device__ __forceinline__ float4 f4add(float4 a, float4 b) {
    return make_float4(a.x + b.x, a.y + b.y, a.z + b.z, a.w + b.w);
}

// ---------------------------------------------------------------------------
// CSR build
// ---------------------------------------------------------------------------
__global__ void k_zero() {
    int i = blockIdx.x * blockDim.x + threadIdx.x;
    if (i < NN) { g_degi[i] = 0; g_cursor[i] = 0; }
}
__global__ void k_count(const int* __restrict__ dst) {
    int e = blockIdx.x * blockDim.x + threadIdx.x;
    if (e < EE) atomicAdd(&g_degi[dst[e]], 1);
}
__global__ void k_invdeg() {
    int i = blockIdx.x * blockDim.x + threadIdx.x;
    if (i < NN) g_invdeg[i] = 1.f / fmaxf((float)g_degi[i], 1.f);
}
// single-block exclusive prefix sum over g_degi -> g_rowptr
__global__ void k_scan() {
    __shared__ int ssum[1024];
    const int tid = threadIdx.x;
    const int per = (NN + 1023) / 1024;   // 20
    const int base = tid * per;
    int s = 0;
#pragma unroll 4
    for (int j = 0; j < per; j++) {
        int idx = base + j;
        if (idx < NN) s += g_degi[idx];
    }
    ssum[tid] = s;
    __syncthreads();
    for (int off = 1; off < 1024; off <<= 1) {
        int v = 0;
        if (tid >= off) v = ssum[tid - off];
        __syncthreads();
        ssum[tid] += v;
        __syncthreads();
    }
    int run = ssum[tid] - s;   // exclusive
#pragma unroll 4
    for (int j = 0; j < per; j++) {
        int idx = base + j;
        if (idx < NN) { g_rowptr[idx] = run; run += g_degi[idx]; }
    }
    if (tid == 1023) g_rowptr[NN] = EE;
}
__global__ void k_fill(const int* __restrict__ src, const int* __restrict__ dst) {
    int e = blockIdx.x * blockDim.x + threadIdx.x;
    if (e < EE) {
        int d = dst[e];
        int idx = atomicAdd(&g_cursor[d], 1);
        g_csrc[g_rowptr[d] + idx] = src[e];
    }
}

// ---------------------------------------------------------------------------
__global__ void k_embed(const int* __restrict__ tok, const int* __restrict__ pos,
                        const float4* __restrict__ ve, const float4* __restrict__ pe) {
    unsigned t = blockIdx.x * blockDim.x + threadIdx.x;
    unsigned i = t >> 7, c = t & 127u;
    if (i < NN) {
        g_X4[i * 128 + c] = f4add(ve[(unsigned)tok[i] * 128 + c],
                                  pe[(unsigned)pos[i] * 128 + c]);
    }
}

__device__ __forceinline__ unsigned pack_hl(float a, float b, unsigned& lo) {
    __nv_bfloat162 h = __floats2bfloat162_rn(a, b);
    float2 hf = __bfloat1622float2(h);
    __nv_bfloat162 l = __floats2bfloat162_rn(a - hf.x, b - hf.y);
    lo = *reinterpret_cast<unsigned*>(&l);
    return *reinterpret_cast<unsigned*>(&h);
}

// BN (eval) -> g_Xbn fp32 (gather source) + bf16 hi/lo A cols 512-1023
__global__ void k_bn(const float4* __restrict__ ga, const float4* __restrict__ be,
                     const float4* __restrict__ me, const float4* __restrict__ va) {
    unsigned t = blockIdx.x * blockDim.x + threadIdx.x;
    unsigned i = t >> 7, c = t & 127u;
    if (i >= NN) return;
    float4 x = g_X4[i * 128 + c];
    float4 g = ga[c], b = be[c], m = me[c], v = va[c];
    float4 y;
    y.x = (x.x - m.x) * (g.x * rsqrtf(v.x + BN_EPS)) + b.x;
    y.y = (x.y - m.y) * (g.y * rsqrtf(v.y + BN_EPS)) + b.y;
    y.z = (x.z - m.z) * (g.z * rsqrtf(v.z + BN_EPS)) + b.z;
    y.w = (x.w - m.w) * (g.w * rsqrtf(v.w + BN_EPS)) + b.w;
    g_Xbn[i * 128 + c] = y;
    unsigned l0, l1;
    unsigned h0 = pack_hl(y.x, y.y, l0);
    unsigned h1 = pack_hl(y.z, y.w, l1);
    size_t o = (size_t)i * 1024 + 512 + c * 4;
    *(uint2*)&g_Ah[o] = make_uint2(h0, h1);
    *(uint2*)&g_Al[o] = make_uint2(l0, l1);
}

// ---------------------------------------------------------------------------
// CSR gather-aggregate: agg[i] = invdeg * sum_{e} Xbn[csrc[e]]
// -> bf16 hi/lo A cols 0-511.   2 nodes per CTA; thread = one float4 column.
// ---------------------------------------------------------------------------
__global__ __launch_bounds__(256) void k_gather() {
    const unsigned i = blockIdx.x * 2 + (threadIdx.x >> 7);
    const unsigned c = threadIdx.x & 127u;
    if (i >= NN) return;
    const int r0 = g_rowptr[i], r1 = g_rowptr[i + 1];
    float4 a0 = make_float4(0.f, 0.f, 0.f, 0.f);
    float4 a1 = a0;
    int e = r0;
    for (; e + 1 < r1; e += 2) {
        int s0 = __ldg(&g_csrc[e]);
        int s1 = __ldg(&g_csrc[e + 1]);
        float4 v0 = __ldg(&g_Xbn[(size_t)s0 * 128 + c]);
        float4 v1 = __ldg(&g_Xbn[(size_t)s1 * 128 + c]);
        a0 = f4add(a0, v0);
        a1 = f4add(a1, v1);
    }
    if (e < r1) {
        int s0 = __ldg(&g_csrc[e]);
        a0 = f4add(a0, __ldg(&g_Xbn[(size_t)s0 * 128 + c]));
    }
    a0 = f4add(a0, a1);
    const float sc = g_invdeg[i];
    a0.x *= sc; a0.y *= sc; a0.z *= sc; a0.w *= sc;
    unsigned l0, l1;
    unsigned h0 = pack_hl(a0.x, a0.y, l0);
    unsigned h1 = pack_hl(a0.z, a0.w, l1);
    size_t o = (size_t)i * 1024 + c * 4;
    *(uint2*)&g_Ah[o] = make_uint2(h0, h1);
    *(uint2*)&g_Al[o] = make_uint2(l0, l1);
}

// One-time: split W = [Wrel | Wroot] into bf16 hi/lo planes [l][n][1024].
__global__ void k_wconv(const float* __restrict__ Wrel, const float* __restrict__ Wroot) {
    unsigned t = blockIdx.x * blockDim.x + threadIdx.x;
    if (t >= 4u * 512u * 1024u / 4u) return;
    unsigned base = t * 4u;
    unsigned l = base >> 19;
    unsigned rem = base & 0x7FFFFu;
    unsigned n = rem >> 10;
    unsigned k = rem & 1023u;
    const float* srcp = (k < 512u)
        ? (Wrel + ((size_t)l * 512 + n) * 512 + k)
        : (Wroot + ((size_t)l * 512 + n) * 512 + (k - 512u));
    float4 v = *(const float4*)srcp;
    unsigned l0, l1;
    unsigned h0 = pack_hl(v.x, v.y, l0);
    unsigned h1 = pack_hl(v.z, v.w, l1);
    *(uint2*)&g_Wh[base] = make_uint2(h0, h1);
    *(uint2*)&g_Wl[base] = make_uint2(l0, l1);
}

// ===========================================================================
// mma.sync bf16 GEMM, 3-term split, CTA 128x128, Kc=32.
// cp.async 3-stage pipeline, ONE __syncthreads per chunk, zero in-loop cvt.
// 8 warps (2m x 4n), warp tile 64x32. ROWB=80 -> conflict-free ldmatrix.
// ===========================================================================
#define ROWB 80
#define S_AH 0
#define S_AL 10240
#define S_BH 20480
#define S_BL 30720
#define STAGE 40960
#define SMEM_DYN 122880

__device__ __forceinline__ uint32_t smem_u32(const void* p) {
    uint32_t a;
    asm("{ .reg .u64 t; cvta.to.shared.u64 t, %1; cvt.u32.u64 %0, t; }"
        : "=r"(a) : "l"(p));
    return a;
}
__device__ __forceinline__ void cpa16(uint32_t dst, const void* src, int sbytes) {
    asm volatile("cp.async.ca.shared.global [%0], [%1], 16, %2;"
                 :: "r"(dst), "l"(src), "r"(sbytes) : "memory");
}
__device__ __forceinline__ void ldm_x4(uint32_t* r, uint32_t addr) {
    asm volatile("ldmatrix.sync.aligned.m8n8.x4.shared.b16 {%0,%1,%2,%3}, [%4];"
                 : "=r"(r[0]), "=r"(r[1]), "=r"(r[2]), "=r"(r[3]) : "r"(addr));
}
__device__ __forceinline__ void mma16816(float* c, const uint32_t* a,
                                         uint32_t b0, uint32_t b1) {
    asm volatile(
        "mma.sync.aligned.m16n8k16.row.col.f32.bf16.bf16.f32 "
        "{%0,%1,%2,%3}, {%4,%5,%6,%7}, {%8,%9}, {%0,%1,%2,%3};"
        : "+f"(c[0]), "+f"(c[1]), "+f"(c[2]), "+f"(c[3])
        : "r"(a[0]), "r"(a[1]), "r"(a[2]), "r"(a[3]), "r"(b0), "r"(b1));
}

__global__ __launch_bounds__(256, 1) void k_gemm_mma(
    int lidx, const float* __restrict__ bias, float* __restrict__ outp, int writeX) {
    extern __shared__ char sm[];
    const uint32_t smb = smem_u32(sm);

    const int tid = threadIdx.x;
    const int w = tid >> 5, lane = tid & 31;
    const int row0 = blockIdx.y * 128;
    const int nb0 = blockIdx.x * 128;

    // ---- async-copy mapping: row = tid>>1, 32B half = (tid&1)*32 ----
    const int crow = tid >> 1;
    const int csp = (tid & 1) * 32;
    const int agr = row0 + crow;
    const int abytes = (agr < NN) ? 16 : 0;
    const char* pAh = (const char*)g_Ah + ((size_t)agr * 2048) + csp;
    const char* pAl = (const char*)g_Al + ((size_t)agr * 2048) + csp;
    const char* pWh = (const char*)(g_Wh + ((size_t)lidx * 512 + nb0 + crow) * 1024) + csp;
    const char* pWl = (const char*)(g_Wl + ((size_t)lidx * 512 + nb0 + crow) * 1024) + csp;
    const uint32_t sdst = smb + crow * ROWB + csp;

#define ISSUE(C)                                                              \
    {                                                                         \
        const int c_ = (C);                                                   \
        const uint32_t sb_ = ((c_) % 3) * STAGE;                              \
        const int go_ = c_ * 64;                                              \
        cpa16(sdst + sb_ + S_AH,      pAh + go_,      abytes);                \
        cpa16(sdst + sb_ + S_AH + 16, pAh + go_ + 16, abytes);                \
        cpa16(sdst + sb_ + S_AL,      pAl + go_,      abytes);                \
        cpa16(sdst + sb_ + S_AL + 16, pAl + go_ + 16, abytes);                \
        cpa16(sdst + sb_ + S_BH,      pWh + go_,      16);                    \
        cpa16(sdst + sb_ + S_BH + 16, pWh + go_ + 16, 16);                    \
        cpa16(sdst + sb_ + S_BL,      pWl + go_,      16);                    \
        cpa16(sdst + sb_ + S_BL + 16, pWl + go_ + 16, 16);                    \
        asm volatile("cp.async.commit_group;" ::: "memory");                  \
    }

    // ---- compute mapping: warp grid 2m x 4n, warp tile 64x32 ----
    const int wm0 = (w >> 2) * 64;
    const int wn0 = (w & 3) * 32;
    const int l8 = lane & 7, lq = lane >> 3;

    float acc[4][4][4];
#pragma unroll
    for (int i = 0; i < 4; i++)
#pragma unroll
        for (int j = 0; j < 4; j++)
#pragma unroll
            for (int k = 0; k < 4; k++) acc[i][j][k] = 0.f;

    ISSUE(0);
    ISSUE(1);

#pragma unroll 1
    for (int c = 0; c < 32; ++c) {
        if (c < 30) {
            asm volatile("cp.async.wait_group 1;" ::: "memory");
        } else {
            asm volatile("cp.async.wait_group 0;" ::: "memory");
        }
        __syncthreads();
        if (c < 30) ISSUE(c + 2);

        const uint32_t sb = smb + (c % 3) * STAGE;
#pragma unroll
        for (int ks = 0; ks < 2; ++ks) {
            const int kb = ks * 32;
            uint32_t ah[4][4], al[4][4], bh[2][4], bl[2][4];
            const int ar = wm0 + (lq & 1) * 8 + l8;
            const uint32_t akb = kb + (lq >> 1) * 16;
#pragma unroll
            for (int mi = 0; mi < 4; mi++) {
                uint32_t addr = sb + (ar + mi * 16) * ROWB + akb;
                ldm_x4(ah[mi], addr + S_AH);
                ldm_x4(al[mi], addr + S_AL);
            }
            const int br = wn0 + (lq >> 1) * 8 + l8;
            const uint32_t bkb = kb + (lq & 1) * 16;
#pragma unroll
            for (int ng = 0; ng < 2; ng++) {
                uint32_t addr = sb + (br + ng * 16) * ROWB + bkb;
                ldm_x4(bh[ng], addr + S_BH);
                ldm_x4(bl[ng], addr + S_BL);
            }
#pragma unroll
            for (int mi = 0; mi < 4; mi++)
#pragma unroll
                for (int ni = 0; ni < 4; ni++) {
                    const int g = ni >> 1, o = (ni & 1) * 2;
                    mma16816(acc[mi][ni], ah[mi], bh[g][o], bh[g][o + 1]);
                    mma16816(acc[mi][ni], ah[mi], bl[g][o], bl[g][o + 1]);
                    mma16816(acc[mi][ni], al[mi], bh[g][o], bh[g][o + 1]);
                }
        }
    }
#undef ISSUE

    // ---- epilogue: bias + relu, direct float2 stores ----
    float* O = writeX ? (float*)g_X4 : outp;
    const int lg = lane >> 2, lt = lane & 3;
#pragma unroll
    for (int ni = 0; ni < 4; ni++) {
        const int col = nb0 + wn0 + ni * 8 + lt * 2;
        const float b0 = __ldg(&bias[col]);
        const float b1 = __ldg(&bias[col + 1]);
#pragma unroll
        for (int mi = 0; mi < 4; mi++) {
            const int r0 = row0 + wm0 + mi * 16 + lg;
            if (r0 < NN) {
                float2 v;
                v.x = fmaxf(acc[mi][ni][0] + b0, 0.f);
                v.y = fmaxf(acc[mi][ni][1] + b1, 0.f);
                *(float2*)&O[(size_t)r0 * 512 + col] = v;
            }
            const int r1 = r0 + 8;
            if (r1 < NN) {
                float2 v;
                v.x = fmaxf(acc[mi][ni][2] + b0, 0.f);
                v.y = fmaxf(acc[mi][ni][3] + b1, 0.f);
                *(float2*)&O[(size_t)r1 * 512 + col] = v;
            }
        }
    }
}

// ---------------------------------------------------------------------------
extern "C" void kernel_launch(void* const* d_in, const int* in_sizes, int n_in,
                              void* d_out, int out_size) {
    (void)in_sizes; (void)n_in; (void)out_size;
    const int*   tokens = (const int*)d_in[0];
    const int*   pos    = (const int*)d_in[1];
    const int*   ei     = (const int*)d_in[2];
    const int*   src    = ei;
    const int*   dst    = ei + EE;
    const float* ve     = (const float*)d_in[3];
    const float* pe     = (const float*)d_in[4];
    const float* gamma  = (const float*)d_in[5];
    const float* beta   = (const float*)d_in[6];
    const float* mean   = (const float*)d_in[7];
    const float* var    = (const float*)d_in[8];
    const float* Wrel   = (const float*)d_in[9];
    const float* brel   = (const float*)d_in[10];
    const float* Wroot  = (const float*)d_in[11];
    float*       out    = (float*)d_out;

    cudaFuncSetAttribute(k_gemm_mma, cudaFuncAttributeMaxDynamicSharedMemorySize,
                         SMEM_DYN);

    // CSR build (per launch; deterministic up to float-sum order)
    k_zero<<<(NN + 255) / 256, 256>>>();
    k_count<<<(EE + 255) / 256, 256>>>(dst);
    k_invdeg<<<(NN + 255) / 256, 256>>>();
    k_scan<<<1, 1024>>>();
    k_fill<<<(EE + 255) / 256, 256>>>(src, dst);

    k_embed<<<(NN * 128) / 256, 256>>>(tokens, pos, (const float4*)ve, (const float4*)pe);
    k_wconv<<<(4 * 512 * 1024 / 4 + 255) / 256, 256>>>(Wrel, Wroot);

    for (int l = 0; l < 4; l++) {
        k_bn<<<(NN * 128) / 256, 256>>>(
            (const float4*)(gamma + l * DD), (const float4*)(beta + l * DD),
            (const float4*)(mean + l * DD), (const float4*)(var + l * DD));
        k_gather<<<(NN + 1) / 2, 256>>>();
        k_gemm_mma<<<dim3(4, 157), 256, SMEM_DYN>>>(
            l, brel + l * DD, out, (l == 3) ? 0 : 1);
    }
}